// round 1
// baseline (speedup 1.0000x reference)
#include <cuda_runtime.h>
#include <math.h>

// Problem constants (fixed shapes)
#define NN    20000
#define EE    320000
#define INC   128
#define HIDC  64
#define NHEAD 4
#define EDIM  16
#define C1    256   // HEADS*HID (layer-1 width)
#define C2    64    // layer-2 width

// ---------------- static device scratch (no allocations allowed) -------------
__device__ float g_xl1[NN * C1];
__device__ float g_xr1[NN * C1];
__device__ float g_h  [NN * C1];
__device__ float g_xl2[NN * C2];
__device__ float g_xr2[NN * C2];
__device__ int   g_deg[NN];
__device__ int   g_rowptr[NN + 1];
__device__ int   g_cursor[NN];
__device__ int   g_csr_src[EE];
__device__ int   g_csr_eid[EE];

// ---------------- CSR build ---------------------------------------------------
__global__ void k_zero_deg() {
    int i = blockIdx.x * blockDim.x + threadIdx.x;
    if (i < NN) g_deg[i] = 0;
}

__global__ void k_degree(const int* __restrict__ dst) {
    int e = blockIdx.x * blockDim.x + threadIdx.x;
    if (e < EE) atomicAdd(&g_deg[dst[e]], 1);
}

// single-block exclusive scan of g_deg -> g_rowptr / g_cursor  (1024 thr x 20 elems)
__global__ void k_scan() {
    __shared__ int sums[1024];
    const int t = threadIdx.x;
    const int base = t * 20;
    int local[20];
    int tot = 0;
#pragma unroll
    for (int i = 0; i < 20; i++) {
        int idx = base + i;
        int v = (idx < NN) ? g_deg[idx] : 0;
        local[i] = tot;
        tot += v;
    }
    sums[t] = tot;
    __syncthreads();
#pragma unroll
    for (int off = 1; off < 1024; off <<= 1) {
        int v = (t >= off) ? sums[t - off] : 0;
        __syncthreads();
        sums[t] += v;
        __syncthreads();
    }
    int excl = sums[t] - tot;
#pragma unroll
    for (int i = 0; i < 20; i++) {
        int idx = base + i;
        if (idx < NN) {
            int r = excl + local[i];
            g_rowptr[idx] = r;
            g_cursor[idx] = r;
        }
    }
    if (t == 1023) g_rowptr[NN] = EE;
}

__global__ void k_scatter(const int* __restrict__ src, const int* __restrict__ dst) {
    int e = blockIdx.x * blockDim.x + threadIdx.x;
    if (e < EE) {
        int d = dst[e];
        int slot = atomicAdd(&g_cursor[d], 1);
        g_csr_src[slot] = src[e];
        g_csr_eid[slot] = e;
    }
}

// ---------------- fp32 tiled GEMM  C[M,Nc] = A[M,K] @ B[K,Nc] -----------------
// BM=64, BN=64, BK=16, 256 threads, 4x4 microtile.
__device__ __forceinline__ void sgemm_body(const float* __restrict__ A,
                                           const float* __restrict__ B,
                                           float* __restrict__ C,
                                           int M, int Nc, int K) {
    __shared__ float As[16][64 + 1];
    __shared__ float Bs[16][64];

    const int tid = threadIdx.x;
    const int tx = tid & 15;
    const int ty = tid >> 4;
    const int row0 = blockIdx.y * 64;
    const int col0 = blockIdx.x * 64;

    float c[4][4];
#pragma unroll
    for (int i = 0; i < 4; i++)
#pragma unroll
        for (int j = 0; j < 4; j++) c[i][j] = 0.f;

    for (int k0 = 0; k0 < K; k0 += 16) {
        // A tile: 64 rows x 16 cols
        {
            int ar = tid >> 4;   // 0..15
            int ac = tid & 15;   // 0..15
#pragma unroll
            for (int mm = 0; mm < 4; mm++) {
                int m = row0 + ar + mm * 16;
                As[ac][ar + mm * 16] = (m < M) ? A[(size_t)m * K + k0 + ac] : 0.f;
            }
        }
        // B tile: 16 rows x 64 cols
        {
            int br = tid >> 6;   // 0..3
            int bc = tid & 63;   // 0..63
#pragma unroll
            for (int kk = 0; kk < 4; kk++) {
                Bs[br + kk * 4][bc] = B[(size_t)(k0 + br + kk * 4) * Nc + col0 + bc];
            }
        }
        __syncthreads();
#pragma unroll
        for (int k = 0; k < 16; k++) {
            float a[4], b[4];
#pragma unroll
            for (int i = 0; i < 4; i++) a[i] = As[k][ty * 4 + i];
#pragma unroll
            for (int j = 0; j < 4; j++) b[j] = Bs[k][tx * 4 + j];
#pragma unroll
            for (int i = 0; i < 4; i++)
#pragma unroll
                for (int j = 0; j < 4; j++) c[i][j] = fmaf(a[i], b[j], c[i][j]);
        }
        __syncthreads();
    }
#pragma unroll
    for (int i = 0; i < 4; i++) {
        int m = row0 + ty * 4 + i;
        if (m < M) {
#pragma unroll
            for (int j = 0; j < 4; j++)
                C[(size_t)m * Nc + col0 + tx * 4 + j] = c[i][j];
        }
    }
}

__global__ __launch_bounds__(256) void k_proj_xl1(const float* __restrict__ x,
                                                  const float* __restrict__ W) {
    sgemm_body(x, W, g_xl1, NN, C1, INC);
}
__global__ __launch_bounds__(256) void k_proj_xr1(const float* __restrict__ x,
                                                  const float* __restrict__ W) {
    sgemm_body(x, W, g_xr1, NN, C1, INC);
}
__global__ __launch_bounds__(256) void k_proj_xl2(const float* __restrict__ W) {
    sgemm_body(g_h, W, g_xl2, NN, C2, C1);
}
__global__ __launch_bounds__(256) void k_proj_xr2(const float* __restrict__ W) {
    sgemm_body(g_h, W, g_xr2, NN, C2, C1);
}

// ---------------- Layer-1 edge pass: warp per destination node ----------------
// Lane owns channels c = lane + 32*j, j=0..7. Head of channel j is j>>1.
__global__ __launch_bounds__(256)
void k_edge1(const float* __restrict__ eattr,   // [E,16]
             const float* __restrict__ We,      // [16,256]
             const float* __restrict__ att,     // [4,64]
             const float* __restrict__ b1)      // [256]
{
    const int gw   = (blockIdx.x * blockDim.x + threadIdx.x) >> 5;
    const int lane = threadIdx.x & 31;
    if (gw >= NN) return;

    // register-resident We slice for this lane: we[k][j] = We[k][lane+32j]
    float we[16][8];
#pragma unroll
    for (int k = 0; k < 16; k++)
#pragma unroll
        for (int j = 0; j < 8; j++) we[k][j] = We[k * 256 + j * 32 + lane];

    float attv[8];
#pragma unroll
    for (int j = 0; j < 8; j++)
        attv[j] = att[(j >> 1) * 64 + (j & 1) * 32 + lane];

    float xrv[8];
#pragma unroll
    for (int j = 0; j < 8; j++) xrv[j] = g_xr1[gw * 256 + j * 32 + lane];

    float acc[8];
    float m[4], s[4];
#pragma unroll
    for (int j = 0; j < 8; j++) acc[j] = 0.f;
#pragma unroll
    for (int h = 0; h < 4; h++) { m[h] = -1e30f; s[h] = 0.f; }

    const int beg = g_rowptr[gw];
    const int end = g_rowptr[gw + 1];

    for (int i = beg; i < end; i++) {
        const int srcn = g_csr_src[i];
        const int eid  = g_csr_eid[i];
        float ev = (lane < 16) ? eattr[(size_t)eid * 16 + lane] : 0.f;

        float xlv[8], u[8];
#pragma unroll
        for (int j = 0; j < 8; j++) {
            xlv[j] = g_xl1[(size_t)srcn * 256 + j * 32 + lane];
            u[j] = xlv[j] + xrv[j];
        }
        // ea on the fly: u += edge_attr @ We
#pragma unroll
        for (int k = 0; k < 16; k++) {
            float ek = __shfl_sync(0xffffffffu, ev, k);
#pragma unroll
            for (int j = 0; j < 8; j++) u[j] = fmaf(ek, we[k][j], u[j]);
        }
        // LeakyReLU(0.2)
#pragma unroll
        for (int j = 0; j < 8; j++) u[j] = (u[j] > 0.f) ? u[j] : 0.2f * u[j];

        // per-head logits: lane partials then butterfly reduce
        float lg[4];
#pragma unroll
        for (int h = 0; h < 4; h++)
            lg[h] = u[2 * h] * attv[2 * h] + u[2 * h + 1] * attv[2 * h + 1];
#pragma unroll
        for (int off = 16; off > 0; off >>= 1) {
#pragma unroll
            for (int h = 0; h < 4; h++)
                lg[h] += __shfl_xor_sync(0xffffffffu, lg[h], off);
        }
        // online softmax update
        float p[4], sc[4];
#pragma unroll
        for (int h = 0; h < 4; h++) {
            float nm = fmaxf(m[h], lg[h]);
            sc[h] = expf(m[h] - nm);
            p[h]  = expf(lg[h] - nm);
            s[h]  = s[h] * sc[h] + p[h];
            m[h]  = nm;
        }
#pragma unroll
        for (int j = 0; j < 8; j++) {
            int h = j >> 1;
            acc[j] = acc[j] * sc[h] + p[h] * xlv[j];
        }
    }

    // normalize, bias, ELU -> h
#pragma unroll
    for (int j = 0; j < 8; j++) {
        int h = j >> 1;
        float o = (s[h] > 0.f) ? acc[j] / s[h] : 0.f;
        o += b1[j * 32 + lane];
        o = (o > 0.f) ? o : expm1f(o);
        g_h[gw * 256 + j * 32 + lane] = o;
    }
}

// ---------------- Layer-2 edge pass (heads=1, C=64, mean==identity) ----------
__global__ __launch_bounds__(256)
void k_edge2(const float* __restrict__ eattr,   // [E,16]
             const float* __restrict__ We,      // [16,64]
             const float* __restrict__ att,     // [64]
             const float* __restrict__ b2,      // [64]
             float* __restrict__ out)           // [N,64]
{
    const int gw   = (blockIdx.x * blockDim.x + threadIdx.x) >> 5;
    const int lane = threadIdx.x & 31;
    if (gw >= NN) return;

    float we[16][2];
#pragma unroll
    for (int k = 0; k < 16; k++)
#pragma unroll
        for (int j = 0; j < 2; j++) we[k][j] = We[k * 64 + j * 32 + lane];

    float attv[2];
#pragma unroll
    for (int j = 0; j < 2; j++) attv[j] = att[j * 32 + lane];

    float xrv[2];
#pragma unroll
    for (int j = 0; j < 2; j++) xrv[j] = g_xr2[gw * 64 + j * 32 + lane];

    float acc[2] = {0.f, 0.f};
    float m = -1e30f, s = 0.f;

    const int beg = g_rowptr[gw];
    const int end = g_rowptr[gw + 1];

    for (int i = beg; i < end; i++) {
        const int srcn = g_csr_src[i];
        const int eid  = g_csr_eid[i];
        float ev = (lane < 16) ? eattr[(size_t)eid * 16 + lane] : 0.f;

        float xlv[2], u[2];
#pragma unroll
        for (int j = 0; j < 2; j++) {
            xlv[j] = g_xl2[(size_t)srcn * 64 + j * 32 + lane];
            u[j] = xlv[j] + xrv[j];
        }
#pragma unroll
        for (int k = 0; k < 16; k++) {
            float ek = __shfl_sync(0xffffffffu, ev, k);
#pragma unroll
            for (int j = 0; j < 2; j++) u[j] = fmaf(ek, we[k][j], u[j]);
        }
#pragma unroll
        for (int j = 0; j < 2; j++) u[j] = (u[j] > 0.f) ? u[j] : 0.2f * u[j];

        float lg = u[0] * attv[0] + u[1] * attv[1];
#pragma unroll
        for (int off = 16; off > 0; off >>= 1)
            lg += __shfl_xor_sync(0xffffffffu, lg, off);

        float nm = fmaxf(m, lg);
        float sc = expf(m - nm);
        float p  = expf(lg - nm);
        s = s * sc + p;
        m = nm;
#pragma unroll
        for (int j = 0; j < 2; j++) acc[j] = acc[j] * sc + p * xlv[j];
    }

#pragma unroll
    for (int j = 0; j < 2; j++) {
        float o = (s > 0.f) ? acc[j] / s : 0.f;
        out[gw * 64 + j * 32 + lane] = o + b2[j * 32 + lane];
    }
}

// ---------------- launch -----------------------------------------------------
extern "C" void kernel_launch(void* const* d_in, const int* in_sizes, int n_in,
                              void* d_out, int out_size) {
    const float* x     = (const float*)d_in[0];
    const int*   ei    = (const int*)d_in[1];
    const float* eattr = (const float*)d_in[2];
    const float* Wl1   = (const float*)d_in[3];
    const float* Wr1   = (const float*)d_in[4];
    const float* We1   = (const float*)d_in[5];
    const float* att1  = (const float*)d_in[6];
    const float* b1    = (const float*)d_in[7];
    const float* Wl2   = (const float*)d_in[8];
    const float* Wr2   = (const float*)d_in[9];
    const float* We2   = (const float*)d_in[10];
    const float* att2  = (const float*)d_in[11];
    const float* b2    = (const float*)d_in[12];
    float* out = (float*)d_out;

    const int* src = ei;        // edge_index[0]
    const int* dst = ei + EE;   // edge_index[1]

    // CSR build
    k_zero_deg<<<(NN + 255) / 256, 256>>>();
    k_degree<<<(EE + 255) / 256, 256>>>(dst);
    k_scan<<<1, 1024>>>();
    k_scatter<<<(EE + 255) / 256, 256>>>(src, dst);

    // Layer-1 projections: [20000,128] @ [128,256]
    {
        dim3 grid(C1 / 64, (NN + 63) / 64);
        k_proj_xl1<<<grid, 256>>>(x, Wl1);
        k_proj_xr1<<<grid, 256>>>(x, Wr1);
    }

    // Layer-1 edge pass (fused segment softmax + aggregation + bias + ELU)
    k_edge1<<<(NN * 32 + 255) / 256, 256>>>(eattr, We1, att1, b1);

    // Layer-2 projections: [20000,256] @ [256,64]
    {
        dim3 grid(C2 / 64, (NN + 63) / 64);
        k_proj_xl2<<<grid, 256>>>(Wl2);
        k_proj_xr2<<<grid, 256>>>(Wr2);
    }

    // Layer-2 edge pass -> final output
    k_edge2<<<(NN * 32 + 255) / 256, 256>>>(eattr, We2, att2, b2, out);
}

// round 4
// speedup vs baseline: 1.1809x; 1.1809x over previous
#include <cuda_runtime.h>
#include <math.h>

// Fixed problem shapes
#define NN    20000
#define EE    320000
#define INC   128
#define L1C   256   // HEADS*HID (layer-1 width)
#define L2C   64    // layer-2 width

typedef unsigned long long u64;

// ---------------- static device scratch (16B aligned for vector access) ------
__device__ __align__(16) float g_xl1[NN * L1C];
__device__ __align__(16) float g_xr1[NN * L1C];
__device__ __align__(16) float g_h  [NN * L1C];
__device__ __align__(16) float g_xl2[NN * L2C];
__device__ __align__(16) float g_xr2[NN * L2C];
__device__ int   g_deg[NN];
__device__ int   g_rowptr[NN + 1];
__device__ int   g_cursor[NN];
__device__ int   g_csr_src[EE];
__device__ int   g_csr_eid[EE];

// ---------------- f32x2 helpers ----------------
__device__ __forceinline__ u64 pk2(float lo, float hi) {
    u64 r; asm("mov.b64 %0, {%1,%2};" : "=l"(r) : "f"(lo), "f"(hi)); return r;
}
__device__ __forceinline__ u64 dup2(float v) { return pk2(v, v); }
__device__ __forceinline__ void upk2(float& lo, float& hi, u64 v) {
    asm("mov.b64 {%0,%1}, %2;" : "=f"(lo), "=f"(hi) : "l"(v));
}
__device__ __forceinline__ u64 fma2(u64 a, u64 b, u64 c) {
    u64 d; asm("fma.rn.f32x2 %0, %1, %2, %3;" : "=l"(d) : "l"(a), "l"(b), "l"(c)); return d;
}
__device__ __forceinline__ u64 add2(u64 a, u64 b) {
    u64 d; asm("add.rn.f32x2 %0, %1, %2;" : "=l"(d) : "l"(a), "l"(b)); return d;
}
__device__ __forceinline__ u64 mul2(u64 a, u64 b) {
    u64 d; asm("mul.rn.f32x2 %0, %1, %2;" : "=l"(d) : "l"(a), "l"(b)); return d;
}

// ---------------- CSR build ----------------
__global__ void k_zero_deg() {
    int i = blockIdx.x * blockDim.x + threadIdx.x;
    if (i < NN) g_deg[i] = 0;
}
__global__ void k_degree(const int* __restrict__ dst) {
    int e = blockIdx.x * blockDim.x + threadIdx.x;
    if (e < EE) atomicAdd(&g_deg[dst[e]], 1);
}
__global__ void k_scan() {
    __shared__ int sums[1024];
    const int t = threadIdx.x;
    const int base = t * 20;
    int local[20];
    int tot = 0;
#pragma unroll
    for (int i = 0; i < 20; i++) {
        int idx = base + i;
        int v = (idx < NN) ? g_deg[idx] : 0;
        local[i] = tot;
        tot += v;
    }
    sums[t] = tot;
    __syncthreads();
#pragma unroll
    for (int off = 1; off < 1024; off <<= 1) {
        int v = (t >= off) ? sums[t - off] : 0;
        __syncthreads();
        sums[t] += v;
        __syncthreads();
    }
    int excl = sums[t] - tot;
#pragma unroll
    for (int i = 0; i < 20; i++) {
        int idx = base + i;
        if (idx < NN) {
            int r = excl + local[i];
            g_rowptr[idx] = r;
            g_cursor[idx] = r;
        }
    }
    if (t == 1023) g_rowptr[NN] = EE;
}
__global__ void k_scatter(const int* __restrict__ src, const int* __restrict__ dst) {
    int e = blockIdx.x * blockDim.x + threadIdx.x;
    if (e < EE) {
        int d = dst[e];
        int slot = atomicAdd(&g_cursor[d], 1);
        g_csr_src[slot] = src[e];
        g_csr_eid[slot] = e;
    }
}

// ---------------- dual-output SGEMM body (f32x2 FMA) ----------------
// Logical C = A @ [B0 | B1]; columns [0,split) -> out0, [split,ncols) -> out1.
// BM=BN=128, BK=16, 256 threads, 8x8 microtile. out0/out1 must be DEVICE
// addresses taken inside device code (see __global__ wrappers below).
__device__ __forceinline__
void gemm_dual_body(const float* __restrict__ A, int M, int K,
                    const float* __restrict__ B0, const float* __restrict__ B1,
                    int ncols, int split,
                    float* __restrict__ out0, float* __restrict__ out1)
{
    __shared__ float As[16][132];
    __shared__ float Bs[16][128];
    const int tid = threadIdx.x;
    const int tx = tid & 15, ty = tid >> 4;
    const int row0 = blockIdx.y * 128;
    const int n0 = blockIdx.x * 128;
    const int w0 = split, w1 = ncols - split;

    u64 acc[8][4];
#pragma unroll
    for (int i = 0; i < 8; i++)
#pragma unroll
        for (int j = 0; j < 4; j++) acc[i][j] = 0ull;

    const int ar = tid >> 2;        // 0..63
    const int ac = (tid & 3) * 4;   // 0,4,8,12
    const int bk = tid >> 5;        // 0..7
    const int bc = (tid & 31) * 4;  // 0..124

    for (int k0 = 0; k0 < K; k0 += 16) {
#pragma unroll
        for (int p = 0; p < 2; p++) {
            int r = ar + p * 64;
            int gr = row0 + r;
            float4 v = make_float4(0.f, 0.f, 0.f, 0.f);
            if (gr < M) v = *(const float4*)(A + (size_t)gr * K + k0 + ac);
            As[ac + 0][r] = v.x; As[ac + 1][r] = v.y;
            As[ac + 2][r] = v.z; As[ac + 3][r] = v.w;
        }
#pragma unroll
        for (int p = 0; p < 2; p++) {
            int kk = bk + p * 8;
            int gc = n0 + bc;
            const float* srcp = (gc < w0)
                ? (B0 + (size_t)(k0 + kk) * w0 + gc)
                : (B1 + (size_t)(k0 + kk) * w1 + (gc - w0));
            *(float4*)&Bs[kk][bc] = *(const float4*)srcp;
        }
        __syncthreads();
#pragma unroll
        for (int k = 0; k < 16; k++) {
            float4 a0 = *(float4*)&As[k][ty * 8];
            float4 a1 = *(float4*)&As[k][ty * 8 + 4];
            float4 bv0 = *(float4*)&Bs[k][tx * 8];
            float4 bv1 = *(float4*)&Bs[k][tx * 8 + 4];
            u64 bp[4] = { pk2(bv0.x, bv0.y), pk2(bv0.z, bv0.w),
                          pk2(bv1.x, bv1.y), pk2(bv1.z, bv1.w) };
            float av[8] = { a0.x, a0.y, a0.z, a0.w, a1.x, a1.y, a1.z, a1.w };
#pragma unroll
            for (int i = 0; i < 8; i++) {
                u64 ap = dup2(av[i]);
#pragma unroll
                for (int j = 0; j < 4; j++) acc[i][j] = fma2(ap, bp[j], acc[i][j]);
            }
        }
        __syncthreads();
    }
#pragma unroll
    for (int i = 0; i < 8; i++) {
        int gr = row0 + ty * 8 + i;
        if (gr >= M) continue;
#pragma unroll
        for (int j = 0; j < 4; j++) {
            int gc = n0 + tx * 8 + j * 2;
            float lo, hi; upk2(lo, hi, acc[i][j]);
            float2 v = make_float2(lo, hi);
            if (gc < w0) *(float2*)(out0 + (size_t)gr * w0 + gc) = v;
            else         *(float2*)(out1 + (size_t)gr * w1 + (gc - w0)) = v;
        }
    }
}

// Wrappers bind the __device__ scratch arrays INSIDE device code.
__global__ __launch_bounds__(256, 2)
void k_gemm_l1(const float* __restrict__ x,
               const float* __restrict__ Wl1, const float* __restrict__ Wr1) {
    gemm_dual_body(x, NN, INC, Wl1, Wr1, 2 * L1C, L1C, g_xl1, g_xr1);
}
__global__ __launch_bounds__(256, 2)
void k_gemm_l2(const float* __restrict__ Wl2, const float* __restrict__ Wr2) {
    gemm_dual_body(g_h, NN, L1C, Wl2, Wr2, 2 * L2C, L2C, g_xl2, g_xr2);
}

// ---------------- Layer-1 edge pass: 2 warps per node, 2 heads per warp ------
// Warp part p handles heads 2p, 2p+1. Lane owns channels h*64 + 2*lane + {0,1}.
__global__ __launch_bounds__(256)
void k_edge1(const float* __restrict__ eattr,   // [E,16]
             const float* __restrict__ Wep,     // [16,256]
             const float* __restrict__ attp,    // [4,64]
             const float* __restrict__ biasp)   // [256]
{
    const int w    = (blockIdx.x * blockDim.x + threadIdx.x) >> 5;
    const int lane = threadIdx.x & 31;
    const int node = w >> 1;
    const int part = w & 1;
    if (node >= NN) return;
    const int h0 = part * 2;
    const int co0 = h0 * 64 + 2 * lane;
    const int co1 = (h0 + 1) * 64 + 2 * lane;

    u64 we[16][2];
#pragma unroll
    for (int k = 0; k < 16; k++) {
        we[k][0] = *(const u64*)(Wep + k * 256 + co0);
        we[k][1] = *(const u64*)(Wep + k * 256 + co1);
    }
    float2 attv0 = *(const float2*)(attp + h0 * 64 + 2 * lane);
    float2 attv1 = *(const float2*)(attp + (h0 + 1) * 64 + 2 * lane);

    const float* xrbase = g_xr1 + (size_t)node * 256;
    u64 xrv[2] = { *(const u64*)(xrbase + co0), *(const u64*)(xrbase + co1) };

    u64 acc[2] = { 0ull, 0ull };
    float m0 = -1e30f, m1 = -1e30f;
    float s0 = 0.f, s1 = 0.f;

    const int beg = g_rowptr[node];
    const int end = g_rowptr[node + 1];

    for (int i = beg; i < end; i++) {
        const int srcn = g_csr_src[i];
        const int eid  = g_csr_eid[i];
        float ev = (lane < 16) ? eattr[(size_t)eid * 16 + lane] : 0.f;

        const float* xlbase = g_xl1 + (size_t)srcn * 256;
        u64 xlv0 = *(const u64*)(xlbase + co0);
        u64 xlv1 = *(const u64*)(xlbase + co1);
        u64 u20 = add2(xlv0, xrv[0]);
        u64 u21 = add2(xlv1, xrv[1]);

#pragma unroll
        for (int k = 0; k < 16; k++) {
            u64 ekp = dup2(__shfl_sync(0xffffffffu, ev, k));
            u20 = fma2(ekp, we[k][0], u20);
            u21 = fma2(ekp, we[k][1], u21);
        }
        float lg0, lg1;
        {
            float x0, y0, x1, y1;
            upk2(x0, y0, u20); upk2(x1, y1, u21);
            x0 = (x0 > 0.f) ? x0 : 0.2f * x0;  y0 = (y0 > 0.f) ? y0 : 0.2f * y0;
            x1 = (x1 > 0.f) ? x1 : 0.2f * x1;  y1 = (y1 > 0.f) ? y1 : 0.2f * y1;
            lg0 = x0 * attv0.x + y0 * attv0.y;
            lg1 = x1 * attv1.x + y1 * attv1.y;
        }
#pragma unroll
        for (int off = 16; off > 0; off >>= 1) {
            lg0 += __shfl_xor_sync(0xffffffffu, lg0, off);
            lg1 += __shfl_xor_sync(0xffffffffu, lg1, off);
        }
        // online softmax
        {
            float nm = fmaxf(m0, lg0);
            float sc = __expf(m0 - nm);
            float p  = __expf(lg0 - nm);
            s0 = s0 * sc + p;
            m0 = nm;
            acc[0] = fma2(dup2(p), xlv0, mul2(acc[0], dup2(sc)));
        }
        {
            float nm = fmaxf(m1, lg1);
            float sc = __expf(m1 - nm);
            float p  = __expf(lg1 - nm);
            s1 = s1 * sc + p;
            m1 = nm;
            acc[1] = fma2(dup2(p), xlv1, mul2(acc[1], dup2(sc)));
        }
    }

    // normalize + bias + ELU
    float* hbase = g_h + (size_t)node * 256;
    {
        float ax, ay; upk2(ax, ay, acc[0]);
        float inv = (s0 > 0.f) ? 1.f / s0 : 0.f;
        float2 bb = *(const float2*)(biasp + co0);
        float ox = ax * inv + bb.x;
        float oy = ay * inv + bb.y;
        ox = (ox > 0.f) ? ox : (__expf(ox) - 1.f);
        oy = (oy > 0.f) ? oy : (__expf(oy) - 1.f);
        *(float2*)(hbase + co0) = make_float2(ox, oy);
    }
    {
        float ax, ay; upk2(ax, ay, acc[1]);
        float inv = (s1 > 0.f) ? 1.f / s1 : 0.f;
        float2 bb = *(const float2*)(biasp + co1);
        float ox = ax * inv + bb.x;
        float oy = ay * inv + bb.y;
        ox = (ox > 0.f) ? ox : (__expf(ox) - 1.f);
        oy = (oy > 0.f) ? oy : (__expf(oy) - 1.f);
        *(float2*)(hbase + co1) = make_float2(ox, oy);
    }
}

// ---------------- Layer-2 edge pass: warp per node, heads=1, C=64 ------------
__global__ __launch_bounds__(256)
void k_edge2(const float* __restrict__ eattr,   // [E,16]
             const float* __restrict__ Wep,     // [16,64]
             const float* __restrict__ attp,    // [64]
             const float* __restrict__ biasp,   // [64]
             float* __restrict__ outp)          // [N,64]
{
    const int node = (blockIdx.x * blockDim.x + threadIdx.x) >> 5;
    const int lane = threadIdx.x & 31;
    if (node >= NN) return;
    const int co = 2 * lane;

    u64 we[16];
#pragma unroll
    for (int k = 0; k < 16; k++) we[k] = *(const u64*)(Wep + k * 64 + co);
    float2 attv = *(const float2*)(attp + co);
    u64 xrv = *(const u64*)(g_xr2 + (size_t)node * 64 + co);

    u64 acc = 0ull;
    float m = -1e30f, s = 0.f;

    const int beg = g_rowptr[node];
    const int end = g_rowptr[node + 1];

    for (int i = beg; i < end; i++) {
        const int srcn = g_csr_src[i];
        const int eid  = g_csr_eid[i];
        float ev = (lane < 16) ? eattr[(size_t)eid * 16 + lane] : 0.f;

        u64 xlv = *(const u64*)(g_xl2 + (size_t)srcn * 64 + co);
        u64 u2  = add2(xlv, xrv);
#pragma unroll
        for (int k = 0; k < 16; k++) {
            u64 ekp = dup2(__shfl_sync(0xffffffffu, ev, k));
            u2 = fma2(ekp, we[k], u2);
        }
        float x, y; upk2(x, y, u2);
        x = (x > 0.f) ? x : 0.2f * x;
        y = (y > 0.f) ? y : 0.2f * y;
        float lg = x * attv.x + y * attv.y;
#pragma unroll
        for (int off = 16; off > 0; off >>= 1)
            lg += __shfl_xor_sync(0xffffffffu, lg, off);

        float nm = fmaxf(m, lg);
        float sc = __expf(m - nm);
        float p  = __expf(lg - nm);
        s = s * sc + p;
        m = nm;
        acc = fma2(dup2(p), xlv, mul2(acc, dup2(sc)));
    }

    float ax, ay; upk2(ax, ay, acc);
    float inv = (s > 0.f) ? 1.f / s : 0.f;
    float2 bb = *(const float2*)(biasp + co);
    *(float2*)(outp + (size_t)node * 64 + co) =
        make_float2(ax * inv + bb.x, ay * inv + bb.y);
}

// ---------------- launch ----------------
extern "C" void kernel_launch(void* const* d_in, const int* in_sizes, int n_in,
                              void* d_out, int out_size) {
    const float* x     = (const float*)d_in[0];
    const int*   ei    = (const int*)d_in[1];
    const float* eattr = (const float*)d_in[2];
    const float* Wl1   = (const float*)d_in[3];
    const float* Wr1   = (const float*)d_in[4];
    const float* We1   = (const float*)d_in[5];
    const float* att1  = (const float*)d_in[6];
    const float* b1    = (const float*)d_in[7];
    const float* Wl2   = (const float*)d_in[8];
    const float* Wr2   = (const float*)d_in[9];
    const float* We2   = (const float*)d_in[10];
    const float* att2  = (const float*)d_in[11];
    const float* b2    = (const float*)d_in[12];
    float* out = (float*)d_out;

    const int* src = ei;
    const int* dst = ei + EE;

    // CSR build
    k_zero_deg<<<(NN + 255) / 256, 256>>>();
    k_degree<<<(EE + 255) / 256, 256>>>(dst);
    k_scan<<<1, 1024>>>();
    k_scatter<<<(EE + 255) / 256, 256>>>(src, dst);

    // Layer-1 fused projections: [20000,128] @ [128, 256|256]
    {
        dim3 grid(4, (NN + 127) / 128);
        k_gemm_l1<<<grid, 256>>>(x, Wl1, Wr1);
    }

    // Layer-1 edge pass
    k_edge1<<<(NN * 2 * 32 + 255) / 256, 256>>>(eattr, We1, att1, b1);

    // Layer-2 fused projections: [20000,256] @ [256, 64|64]
    {
        dim3 grid(1, (NN + 127) / 128);
        k_gemm_l2<<<grid, 256>>>(Wl2, Wr2);
    }

    // Layer-2 edge pass -> output
    k_edge2<<<(NN * 32 + 255) / 256, 256>>>(eattr, We2, att2, b2, out);
}